// round 17
// baseline (speedup 1.0000x reference)
#include <cuda_runtime.h>
#include <cuda_bf16.h>
#include <cstdint>

#define N_TYPES 8
#define D 64
#define BM 64
#define E_MAX 1048576
typedef unsigned long long ull;

// ---------------- scratch ------------------------------------------------------
__device__ int g_cursor[N_TYPES];
__device__ int g_perm[N_TYPES * E_MAX];  // fixed region per type
// precomputed B fragments: [type][plane][ks][nt][lane] as uint2
__device__ uint2 g_bfrag[N_TYPES * 2 * 4 * 8 * 32];

// ---------------- helpers ------------------------------------------------------
__device__ __forceinline__ uint32_t bf16x2(float x0, float x1) {
    uint32_t r;
    asm("cvt.rn.bf16x2.f32 %0, %1, %2;" : "=r"(r) : "f"(x1), "f"(x0));
    return r;
}
__device__ __forceinline__ float lo_of(uint32_t w) { return __uint_as_float(w << 16); }
__device__ __forceinline__ float hi_of(uint32_t w) {
    return __uint_as_float(w & 0xffff0000u);
}
__device__ __forceinline__ void mma_bf16(float* c, const uint32_t* a,
                                         const uint32_t* b) {
    asm volatile(
        "mma.sync.aligned.m16n8k16.row.col.f32.bf16.bf16.f32 "
        "{%0,%1,%2,%3}, {%4,%5,%6,%7}, {%8,%9}, {%0,%1,%2,%3};"
        : "+f"(c[0]), "+f"(c[1]), "+f"(c[2]), "+f"(c[3])
        : "r"(a[0]), "r"(a[1]), "r"(a[2]), "r"(a[3]), "r"(b[0]), "r"(b[1]));
}
__device__ __forceinline__ void ldmx4(uint32_t* r, uint32_t addr) {
    asm volatile("ldmatrix.sync.aligned.m8n8.x4.shared.b16 {%0,%1,%2,%3}, [%4];"
                 : "=r"(r[0]), "=r"(r[1]), "=r"(r[2]), "=r"(r[3])
                 : "r"(addr));
}
__device__ __forceinline__ uint32_t smem_u32(const void* p) {
    uint32_t a;
    asm("{ .reg .u64 t; cvta.to.shared.u64 t, %1; cvt.u32.u64 %0, t; }"
        : "=r"(a) : "l"(p));
    return a;
}
__device__ __forceinline__ void cp_async16(uint32_t dst, const void* src) {
    asm volatile("cp.async.cg.shared.global [%0], [%1], 16;" ::"r"(dst), "l"(src)
                 : "memory");
}
__device__ __forceinline__ void cp_commit() {
    asm volatile("cp.async.commit_group;" ::: "memory");
}
__device__ __forceinline__ void cp_wait0() {
    asm volatile("cp.async.wait_group 0;" ::: "memory");
}
__device__ __forceinline__ ull pack_f2(float x, float y) {
    ull r;
    asm("mov.b64 %0, {%1, %2};" : "=l"(r) : "f"(x), "f"(y));
    return r;
}
__device__ __forceinline__ void unpack_f2(ull v, float& x, float& y) {
    asm("mov.b64 {%0, %1}, %2;" : "=f"(x), "=f"(y) : "l"(v));
}

// ---------------- launch 0: zero cursors ---------------------------------------
__global__ void k_init() {
    if (threadIdx.x < N_TYPES) g_cursor[threadIdx.x] = 0;
}

// ---------------- launch 1: scatter (per-block dtype detect) + B-frag build ----
__global__ void k_scatter(const void* __restrict__ types,
                          const float* __restrict__ W, int E) {
    __shared__ int s_cnt[N_TYPES], s_base[N_TYPES];
    __shared__ int s_any;
    int tid = threadIdx.x;
    if (tid == 0) s_any = 0;
    if (tid < N_TYPES) s_cnt[tid] = 0;
    __syncthreads();

    int e = blockIdx.x * blockDim.x + tid;

    // per-block int64-vs-int32 detection: sample odd 32-bit words (always
    // in-bounds for both layouts via e' = e mod E/2). int64 data => all zero.
    if (e < E) {
        int e2 = e % (E >> 1);
        if (((const int*)types)[2 * e2 + 1] != 0) s_any = 1;
    }
    __syncthreads();
    int is64 = s_any ? 0 : 1;

    int t = 0, local = 0;
    int valid = (e < E);
    if (valid) {
        t = is64 ? (int)((const long long*)types)[e] : ((const int*)types)[e];
        local = atomicAdd(&s_cnt[t], 1);
    }
    __syncthreads();
    if (tid < N_TYPES) {
        s_base[tid] = tid * E_MAX + atomicAdd(&g_cursor[tid], s_cnt[tid]);
    }
    __syncthreads();
    if (valid) g_perm[s_base[t] + local] = e;

    // blocks 0..7: build B fragments for type = blockIdx.x
    if (blockIdx.x < N_TYPES) {
        int ty = blockIdx.x;
        const float* Wt = W + (size_t)ty * D * D;
        for (int it = tid; it < 4 * 8 * 32; it += blockDim.x) {
            int ks = it >> 8;
            int nt = (it >> 5) & 7;
            int lane = it & 31;
            int col = nt * 8 + (lane >> 2);
            int k0 = ks * 16 + 2 * (lane & 3);
            float w00 = Wt[k0 * D + col];
            float w01 = Wt[(k0 + 1) * D + col];
            float w10 = Wt[(k0 + 8) * D + col];
            float w11 = Wt[(k0 + 9) * D + col];
            uint32_t b0h = bf16x2(w00, w01);
            uint32_t b1h = bf16x2(w10, w11);
            uint32_t b0l = bf16x2(w00 - lo_of(b0h), w01 - hi_of(b0h));
            uint32_t b1l = bf16x2(w10 - lo_of(b1h), w11 - hi_of(b1h));
            g_bfrag[(((ty * 2 + 0) * 4 + ks) * 8 + nt) * 32 + lane] =
                make_uint2(b0h, b1h);
            g_bfrag[(((ty * 2 + 1) * 4 + ks) * 8 + nt) * 32 + lane] =
                make_uint2(b0l, b1l);
        }
    }
}

// ---------------- launch 2: persistent pipelined GEMM, 6 CTAs/SM ---------------
// 128 threads, BM=64, 4 warps (2m x 2n).
// smem: A planes 16KB | Xf32 single buffer 16KB | perm 2x64 ints
static constexpr int SM_X = 16384;
static constexpr int SM_PERM = 32768;
static constexpr int SMEM_DYN = 33280 + 1024;
static constexpr int NCTA = 888;

struct TileInfo {
    int type, row_start, m;
};

__device__ __forceinline__ TileInfo map_tile(int tl) {
    TileInfo ti;
    ti.type = -1;
    ti.row_start = 0;
    ti.m = 0;
    int acc_tiles = 0;
#pragma unroll
    for (int t = 0; t < N_TYPES; t++) {
        int c = g_cursor[t];
        int nt = (c + BM - 1) / BM;
        if (ti.type < 0 && tl < acc_tiles + nt) {
            ti.type = t;
            int lt = tl - acc_tiles;
            ti.row_start = t * E_MAX + lt * BM;
            ti.m = c - lt * BM;
            if (ti.m > BM) ti.m = BM;
        }
        acc_tiles += nt;
    }
    return ti;
}

__global__ void __launch_bounds__(128, 6) k_gemm_mma(const float* __restrict__ X,
                                                     const float* __restrict__ Bv,
                                                     float* __restrict__ out) {
    extern __shared__ char sm_raw[];
    uint32_t raw = smem_u32(sm_raw);
    uint32_t base = (raw + 1023) & ~1023u;
    char* pbase = sm_raw + (base - raw);
    uint32_t sA = base;
    uint32_t sX = base + SM_X;
    char* pX = pbase + SM_X;
    int* pperm = reinterpret_cast<int*>(pbase + SM_PERM);  // [2][64]

    int tid = threadIdx.x;
    int lane = tid & 31;
    int w = tid >> 5;  // 0..3

    int ntiles = 0;
#pragma unroll
    for (int t = 0; t < N_TYPES; t++) ntiles += (g_cursor[t] + BM - 1) / BM;

    // lane maps
    int sub = lane >> 4;
    int q = lane & 15;
    int gc = q >> 1;
    int gsb = (q & 1) * 8;
    int wm = (w & 1) * 32;
    int wnq = (w >> 1) & 1;
    int wn = wnq * 32;
    int group = lane >> 2;
    int qc = lane & 3;
    int lrow[2];
#pragma unroll
    for (int mt = 0; mt < 2; mt++) lrow[mt] = wm + mt * 16 + (lane & 15);
    int cadd = lane >> 4;

    int tl = blockIdx.x;
    if (tl >= ntiles) return;

    // ---- prologue ----
    TileInfo cur = map_tile(tl);
    if (tid < BM) {
        int rr = (tid < cur.m) ? tid : (cur.m - 1);
        pperm[tid] = g_perm[cur.row_start + rr];
    }
    __syncthreads();
#pragma unroll
    for (int s = 0; s < 8; s++) {
        int r = s * 8 + w * 2 + sub;
        int e = pperm[r];
        cp_async16(sX + r * 256 + q * 16, X + (size_t)e * D + q * 4);
    }
    cp_commit();
    cp_wait0();
    __syncthreads();

    int buf = 0;
    int btype = -1;
    float2 bias[4];

    for (; tl < ntiles; tl += NCTA) {
        // ---- bias cache (reload on type change only) ----
        if (cur.type != btype) {
            btype = cur.type;
#pragma unroll
            for (int nt = 0; nt < 4; nt++) {
                bias[nt] = *reinterpret_cast<const float2*>(
                    Bv + (size_t)btype * D + wn + nt * 8 + qc * 2);
            }
        }

        // ---- convert Xf32 -> bf16 planes in A ----
#pragma unroll
        for (int s = 0; s < 8; s++) {
            int r = s * 8 + w * 2 + sub;
            float4 v = *reinterpret_cast<const float4*>(pX + r * 256 + q * 16);
            uint32_t h0 = bf16x2(v.x, v.y);
            uint32_t h1 = bf16x2(v.z, v.w);
            uint32_t l0 = bf16x2(v.x - lo_of(h0), v.y - hi_of(h0));
            uint32_t l1 = bf16x2(v.z - lo_of(h1), v.w - hi_of(h1));
            uint32_t off = (uint32_t)r * 128 + (uint32_t)((gc ^ (r & 7)) << 4) + gsb;
            *reinterpret_cast<uint2*>(pbase + off) = make_uint2(h0, h1);
            *reinterpret_cast<uint2*>(pbase + 8192 + off) = make_uint2(l0, l1);
        }

        // ---- prefetch next tile's perm ----
        int tln = tl + NCTA;
        bool hasnext = (tln < ntiles);
        TileInfo nxt;
        if (hasnext) {
            nxt = map_tile(tln);
            if (tid < BM) {
                int rr = (tid < nxt.m) ? tid : (nxt.m - 1);
                pperm[(buf ^ 1) * BM + tid] = g_perm[nxt.row_start + rr];
            }
        }
        __syncthreads();  // A visible; X fully consumed

        // ---- gather next tile into the same X buffer ----
        if (hasnext) {
            const int* pp = pperm + (buf ^ 1) * BM;
#pragma unroll
            for (int s = 0; s < 8; s++) {
                int r = s * 8 + w * 2 + sub;
                int e = pp[r];
                cp_async16(sX + r * 256 + q * 16, X + (size_t)e * D + q * 4);
            }
        }
        cp_commit();

        // ---- MMA: per-nt serialized B ----
        const uint2* gB = g_bfrag + (size_t)cur.type * 2048;

        float acc[2][4][4];
#pragma unroll
        for (int mt = 0; mt < 2; mt++)
#pragma unroll
            for (int nt = 0; nt < 4; nt++)
#pragma unroll
                for (int i = 0; i < 4; i++) acc[mt][nt][i] = 0.0f;

#pragma unroll
        for (int ks = 0; ks < 4; ks++) {
            uint32_t a[2][2][4];  // [plane][mt][reg]
#pragma unroll
            for (int mt = 0; mt < 2; mt++) {
                int c = ks * 2 + cadd;
                uint32_t off =
                    (uint32_t)lrow[mt] * 128 + (uint32_t)((c ^ (lrow[mt] & 7)) << 4);
                ldmx4(a[0][mt], sA + off);
                ldmx4(a[1][mt], sA + 8192 + off);
            }
#pragma unroll
            for (int nt = 0; nt < 4; nt++) {
                uint32_t b[2];
                {
                    uint2 v = __ldg(&gB[((0 * 4 + ks) * 8 + wnq * 4 + nt) * 32 + lane]);
                    b[0] = v.x;
                    b[1] = v.y;
                }
                mma_bf16(acc[0][nt], a[0][0], b);  // hi_a * hi_b
                mma_bf16(acc[1][nt], a[0][1], b);
                mma_bf16(acc[0][nt], a[1][0], b);  // lo_a * hi_b
                mma_bf16(acc[1][nt], a[1][1], b);
                {
                    uint2 v = __ldg(&gB[((1 * 4 + ks) * 8 + wnq * 4 + nt) * 32 + lane]);
                    b[0] = v.x;
                    b[1] = v.y;
                }
                mma_bf16(acc[0][nt], a[0][0], b);  // hi_a * lo_b
                mma_bf16(acc[1][nt], a[0][1], b);
            }
        }

        // ---- epilogue: bias + relu, quad-shuffle transpose, coalesced STG.128 --
        const int* ppc = pperm + buf * BM;
        unsigned fullm = 0xffffffffu;
#pragma unroll
        for (int mt = 0; mt < 2; mt++) {
#pragma unroll
            for (int half = 0; half < 2; half++) {
                // pack bias+relu'd float2 per nt
                ull tq[4];
#pragma unroll
                for (int nt = 0; nt < 4; nt++) {
                    float v0 = fmaxf(acc[mt][nt][half * 2 + 0] + bias[nt].x, 0.0f);
                    float v1 = fmaxf(acc[mt][nt][half * 2 + 1] + bias[nt].y, 0.0f);
                    tq[nt] = pack_f2(v0, v1);
                }
                // 4x4 quad transpose (phase xor1 then xor2)
                {
                    ull sA1 = (qc & 1) ? tq[0] : tq[1];
                    sA1 = __shfl_xor_sync(fullm, sA1, 1);
                    if (qc & 1) tq[0] = sA1; else tq[1] = sA1;
                    ull sB1 = (qc & 1) ? tq[2] : tq[3];
                    sB1 = __shfl_xor_sync(fullm, sB1, 1);
                    if (qc & 1) tq[2] = sB1; else tq[3] = sB1;
                    ull sC1 = (qc & 2) ? tq[0] : tq[2];
                    sC1 = __shfl_xor_sync(fullm, sC1, 2);
                    if (qc & 2) tq[0] = sC1; else tq[2] = sC1;
                    ull sD1 = (qc & 2) ? tq[1] : tq[3];
                    sD1 = __shfl_xor_sync(fullm, sD1, 2);
                    if (qc & 2) tq[1] = sD1; else tq[3] = sD1;
                }
                // lane qc now holds cols wn + qc*8 + 0..7 of row r
                int r = wm + mt * 16 + group + half * 8;
                if (r < cur.m) {
                    int e = ppc[r];
                    float* op = out + (size_t)e * D + wn + qc * 8;
                    float x0, y0, x1, y1;
                    unpack_f2(tq[0], x0, y0);
                    unpack_f2(tq[1], x1, y1);
                    *reinterpret_cast<float4*>(op) = make_float4(x0, y0, x1, y1);
                    unpack_f2(tq[2], x0, y0);
                    unpack_f2(tq[3], x1, y1);
                    *reinterpret_cast<float4*>(op + 4) = make_float4(x0, y0, x1, y1);
                }
            }
        }

        cp_wait0();
        __syncthreads();
        cur = nxt;
        buf ^= 1;
    }
}

// ---------------- launch -------------------------------------------------------
extern "C" void kernel_launch(void* const* d_in, const int* in_sizes, int n_in,
                              void* d_out, int out_size) {
    const float* X = (const float*)d_in[0];
    const void* types = d_in[1];
    const float* W = (const float*)d_in[2];
    const float* Bv = (const float*)d_in[3];
    float* out = (float*)d_out;
    int E = in_sizes[0] / D;

    cudaFuncSetAttribute(k_gemm_mma, cudaFuncAttributeMaxDynamicSharedMemorySize,
                         SMEM_DYN);
    cudaFuncSetAttribute(k_gemm_mma,
                         cudaFuncAttributePreferredSharedMemoryCarveout, 100);

    k_init<<<1, 32>>>();
    k_scatter<<<(E + 255) / 256, 256>>>(types, W, E);

    k_gemm_mma<<<NCTA, 128, SMEM_DYN>>>(X, Bv, out);
}